// round 17
// baseline (speedup 1.0000x reference)
#include <cuda_runtime.h>
#include <math_constants.h>

// Chamfer loss: N=8, V=4096, C=3 — bucket-windowed exact NN, smem-staged.
// R15 lesson: ring expansion spent ~2/3 of issue slots on control flow.
// Now: phase 1 scans the query's own bucket for an upper bound ub on the
// NN squared distance; phase 2 computes ONE contiguous bucket window
// [kl,kr] covering radius sqrt(ub) and scans it as a single flat loop
// (buckets are contiguous in the binned array). Gram-form body:
// s = q.t - 0.5||t||^2, d^2 = -2*(qw + max s), 5 slots per target.
// Exact: window over-inclusion is harmless; edge clamps cover outliers;
// empty own bucket -> ub=inf -> full scan. Deterministic: min is exact
// order-independent; final sum runs over ORIGINAL point indices.

#define NB 8
#define VPTS 4096
#define NBKT 128
#define XMIN (-4.0f)
#define BW (0.0625f)
#define INVBW (16.0f)
#define NSETS 16              // 2 sets x 8 batches
#define NQTOT (2 * NB * VPTS) // 65536
#define CTHREADS 128
#define CBLOCKS (NQTOT / CTHREADS)   // 512 (32 blocks per (set,batch))

__device__ float4   g_pts[NSETS * VPTS];  // binned; .w = -0.5*||p||^2
__device__ int      g_idx[NSETS * VPTS];  // binned -> original index
__device__ int      g_bstart[NSETS * (NBKT + 1)];
__device__ float    g_dist[NQTOT];        // per-query NN distance, orig order
__device__ unsigned g_cnt_final;          // zero-init; reset after use

__device__ __forceinline__ int bucket_of(float v) {
    int b = (int)floorf((v - XMIN) * INVBW);
    return min(NBKT - 1, max(0, b));
}

// ---------------- binning: one block per (set,batch) ----------------
__global__ __launch_bounds__(256)
void bin_kernel(const float* __restrict__ x, const float* __restrict__ y) {
    const int bi = blockIdx.x;            // 0..15: set = bi>>3, batch = bi&7
    const int s  = bi >> 3;
    const int n  = bi & 7;
    const float* __restrict__ P = (s ? y : x) + (size_t)n * VPTS * 3;
    const int tid = threadIdx.x;

    __shared__ int hist[NBKT];
    __shared__ int offs[NBKT];

    if (tid < NBKT) hist[tid] = 0;
    __syncthreads();

    for (int i = tid; i < VPTS; i += 256)
        atomicAdd(&hist[bucket_of(P[3 * i])], 1);
    __syncthreads();

    if (tid == 0) {
        int run = 0;
        for (int k = 0; k < NBKT; k++) {
            g_bstart[bi * (NBKT + 1) + k] = run;
            offs[k] = run;
            run += hist[k];
        }
        g_bstart[bi * (NBKT + 1) + NBKT] = VPTS;
    }
    __syncthreads();

    for (int i = tid; i < VPTS; i += 256) {
        float a = P[3 * i], b = P[3 * i + 1], c = P[3 * i + 2];
        int k = bucket_of(a);
        int pos = atomicAdd(&offs[k], 1);
        g_pts[bi * VPTS + pos] = make_float4(a, b, c,
                                             -0.5f * (a * a + b * b + c * c));
        g_idx[bi * VPTS + pos] = i;
    }
}

// ---------------- windowed NN from smem + fused final reduction ------
extern __shared__ float4 sT[];   // 4096 x 16B = 64KB binned target set

// Gram-form scan: smax = max over window of (q . t - 0.5||t||^2).
__device__ __forceinline__ void scan_flat(int t0, int t1, float4 q,
                                          float& smax) {
    #pragma unroll 4
    for (int t = t0; t < t1; t++) {
        float4 p = sT[t];
        float s = fmaf(q.x, p.x, fmaf(q.y, p.y, fmaf(q.z, p.z, p.w)));
        smax = fmaxf(smax, s);
    }
}

__global__ __launch_bounds__(CTHREADS)
void chamfer_windowed(float* __restrict__ out) {
    const int tid = threadIdx.x;
    const int qid = blockIdx.x * CTHREADS + tid;   // 0..65535
    const int s   = qid / (NB * VPTS);             // query set
    const int rem = qid - s * (NB * VPTS);
    const int n   = rem / VPTS;
    const int i   = rem - n * VPTS;                // position in binned order

    const int tb = (1 - s) * NB + n;               // target (set,batch)

    // Stage the full binned target set in smem (coalesced fill).
    const float4* __restrict__ TP = g_pts + tb * VPTS;
    #pragma unroll
    for (int p = tid; p < VPTS; p += CTHREADS)
        sT[p] = TP[p];

    // Bucket starts (129 entries -> strided fill covers all).
    __shared__ int sBS[NBKT + 1];
    const int* __restrict__ bs = g_bstart + tb * (NBKT + 1);
    for (int p = tid; p <= NBKT; p += CTHREADS)
        sBS[p] = bs[p];
    __syncthreads();

    const float4 q = g_pts[(s * NB + n) * VPTS + i];   // .w = -0.5||q||^2
    const int k0 = bucket_of(q.x);

    // Phase 1: own bucket -> upper bound.
    float smax = -CUDART_INF_F;
    scan_flat(sBS[k0], sBS[k0 + 1], q, smax);

    // ub on squared NN distance (inf if own bucket empty).
    float ub = fmaxf(-2.0f * (q.w + smax), 0.0f);
    float rl = sqrtf(ub);

    // Phase 2: one contiguous window, flat scan (re-includes own bucket).
    float klf = (q.x - rl - XMIN) * INVBW;
    float krf = (q.x + rl - XMIN) * INVBW;
    int kl = (int)floorf(fminf(fmaxf(klf, 0.0f), (float)(NBKT - 1)));
    int kr = (int)floorf(fminf(fmaxf(krf, 0.0f), (float)(NBKT - 1)));
    scan_flat(sBS[kl], sBS[kr + 1], q, smax);

    const float d = sqrtf(fmaxf(-2.0f * (q.w + smax), 0.0f));

    // write to ORIGINAL index order (deterministic final sum)
    const int orig = g_idx[(s * NB + n) * VPTS + i];
    g_dist[(s * NB + n) * VPTS + orig] = d;
    __threadfence();
    __syncthreads();

    // elect last block for the final deterministic reduction
    __shared__ bool isLast;
    if (tid == 0)
        isLast = (atomicAdd(&g_cnt_final, 1u) == CBLOCKS - 1);
    __syncthreads();

    if (isLast) {
        __threadfence();   // acquire all g_dist writes
        // 65536 floats, 128 threads: 512 consecutive each, fixed order.
        const float4* dv = reinterpret_cast<const float4*>(g_dist) + tid * 128;
        float a0 = 0.f, a1 = 0.f, a2 = 0.f, a3 = 0.f;
        #pragma unroll 4
        for (int j = 0; j < 128; j++) {
            float4 v = dv[j];
            a0 += v.x; a1 += v.y; a2 += v.z; a3 += v.w;
        }
        float v = (a0 + a1) + (a2 + a3);
        #pragma unroll
        for (int off = 16; off > 0; off >>= 1)
            v += __shfl_down_sync(0xffffffffu, v, off);
        __shared__ float ws[CTHREADS / 32];
        if ((tid & 31) == 0) ws[tid >> 5] = v;
        __syncthreads();
        if (tid == 0) {
            float t = 0.f;
            #pragma unroll
            for (int w = 0; w < CTHREADS / 32; w++) t += ws[w];
            out[0] = t * (1.0f / (float)(NB * VPTS));
            g_cnt_final = 0;   // reset for next launch / graph replay
        }
    }
}

extern "C" void kernel_launch(void* const* d_in, const int* in_sizes, int n_in,
                              void* d_out, int out_size) {
    const float* x = (const float*)d_in[0];
    const float* y = (const float*)d_in[1];
    float* out = (float*)d_out;

    bin_kernel<<<NSETS, 256>>>(x, y);

    cudaFuncSetAttribute(chamfer_windowed,
                         cudaFuncAttributeMaxDynamicSharedMemorySize,
                         VPTS * (int)sizeof(float4));
    chamfer_windowed<<<CBLOCKS, CTHREADS, VPTS * sizeof(float4)>>>(out);
}